// round 7
// baseline (speedup 1.0000x reference)
#include <cuda_runtime.h>
#include <cuda_fp16.h>
#include <cstdint>

#define D        128
#define MAXN     100000
#define MAXE     1600000
#define TM       64
#define GTHREADS 256
#define WS_STRIDE 132
#define SCAN_T   256

// -------- device scratch --------
__device__ __half g_h[MAXN * D];      // layer-1 post-GEMM h (normalize*1.8), fp16
__device__ __half g_h2[MAXN * D];     // layer-2 post-GEMM h, fp16 (NO aliasing with g_h)
__device__ int    g_degO[MAXN];
__device__ int    g_degI[MAXN];
__device__ float  g_nO[MAXN];
__device__ float  g_nI[MAXN];
__device__ int    g_rowptr[MAXN + 1];
__device__ int    g_esrc[MAXE];
__device__ int    g_bsum[512];
__device__ int    g_fill[MAXN + 1];

// -------- f32x2 packed-FMA helpers --------
__device__ __forceinline__ unsigned long long fma2(unsigned long long a,
                                                   unsigned long long b,
                                                   unsigned long long c) {
    unsigned long long d;
    asm("fma.rn.f32x2 %0, %1, %2, %3;" : "=l"(d) : "l"(a), "l"(b), "l"(c));
    return d;
}
__device__ __forceinline__ unsigned long long splat2(float x) {
    unsigned long long d;
    asm("mov.b64 %0, {%1, %1};" : "=l"(d) : "f"(x));
    return d;
}
__device__ __forceinline__ void unpack2(unsigned long long v, float& lo, float& hi) {
    asm("mov.b64 {%0, %1}, %2;" : "=f"(lo), "=f"(hi) : "l"(v));
}

// -------- degree --------
__global__ void zero_deg_k(int n) {
    int i = blockIdx.x * blockDim.x + threadIdx.x;
    if (i < n) { g_degO[i] = 0; g_degI[i] = 0; }
}
__global__ void degree_k(const int* __restrict__ src, const int* __restrict__ dst, int E) {
    int e = blockIdx.x * blockDim.x + threadIdx.x;
    if (e < E) { atomicAdd(&g_degO[src[e]], 1); atomicAdd(&g_degI[dst[e]], 1); }
}

// -------- prefix scan over degI -> rowptr; fused norms + cursor seed --------
__global__ void scan_block_k(int n) {
    __shared__ int s[SCAN_T];
    int i = blockIdx.x * SCAN_T + threadIdx.x;
    int v = (i < n) ? g_degI[i] : 0;
    s[threadIdx.x] = v;
    __syncthreads();
    #pragma unroll
    for (int off = 1; off < SCAN_T; off <<= 1) {
        int t = (threadIdx.x >= off) ? s[threadIdx.x - off] : 0;
        __syncthreads();
        s[threadIdx.x] += t;
        __syncthreads();
    }
    if (i < n) g_rowptr[i + 1] = s[threadIdx.x];
    if (threadIdx.x == SCAN_T - 1) g_bsum[blockIdx.x] = s[SCAN_T - 1];
}
__global__ void scan_bsum_k(int nb) {
    __shared__ int s[512];
    int v = (threadIdx.x < nb) ? g_bsum[threadIdx.x] : 0;
    s[threadIdx.x] = v;
    __syncthreads();
    #pragma unroll
    for (int off = 1; off < 512; off <<= 1) {
        int t = (threadIdx.x >= off) ? s[threadIdx.x - off] : 0;
        __syncthreads();
        s[threadIdx.x] += t;
        __syncthreads();
    }
    if (threadIdx.x < nb) g_bsum[threadIdx.x] = s[threadIdx.x] - v;
}
__global__ void scan_add_norm_k(int n) {
    int i = blockIdx.x * SCAN_T + threadIdx.x;
    if (i < n) {
        int v = g_rowptr[i + 1] + g_bsum[blockIdx.x];
        g_rowptr[i + 1] = v;
        g_fill[i + 1]   = v;
        g_nO[i] = rsqrtf(fmaxf((float)g_degO[i], 1.0f));
        g_nI[i] = rsqrtf(fmaxf((float)g_degI[i], 1.0f));
    }
    if (i == 0) { g_rowptr[0] = 0; g_fill[0] = 0; }
}
__global__ void fill_k(const int* __restrict__ src, const int* __restrict__ dst, int E) {
    int e = blockIdx.x * blockDim.x + threadIdx.x;
    if (e < E) {
        int pos = atomicAdd(&g_fill[dst[e]], 1);
        g_esrc[pos] = src[e];
    }
}

// -------- shared GEMM core: acc from xs/ws, epilogue normalize*1.8 -> fp16 --------
__device__ __forceinline__ void gemm_core(const float* __restrict__ ws,
                                          const float* __restrict__ xs,
                                          const float* __restrict__ b,
                                          __half* __restrict__ Hout,
                                          int nb, int N, int tid)
{
    const int cg = tid & 31;
    const int c0 = cg * 4;
    const int n0 = (tid >> 5) * 8;

    unsigned long long acc2[8][2];
    #pragma unroll
    for (int i = 0; i < 8; i++) { acc2[i][0] = 0ull; acc2[i][1] = 0ull; }

    #pragma unroll 4
    for (int k4 = 0; k4 < D / 4; k4++) {
        ulonglong2 wq0 = *(const ulonglong2*)&ws[(4 * k4 + 0) * WS_STRIDE + c0];
        ulonglong2 wq1 = *(const ulonglong2*)&ws[(4 * k4 + 1) * WS_STRIDE + c0];
        ulonglong2 wq2 = *(const ulonglong2*)&ws[(4 * k4 + 2) * WS_STRIDE + c0];
        ulonglong2 wq3 = *(const ulonglong2*)&ws[(4 * k4 + 3) * WS_STRIDE + c0];
        #pragma unroll
        for (int i = 0; i < 8; i++) {
            const float4 xv = *(const float4*)&xs[(n0 + i) * D + 4 * k4];
            unsigned long long x0 = splat2(xv.x);
            unsigned long long x1 = splat2(xv.y);
            unsigned long long x2 = splat2(xv.z);
            unsigned long long x3 = splat2(xv.w);
            acc2[i][0] = fma2(x0, wq0.x, acc2[i][0]);
            acc2[i][1] = fma2(x0, wq0.y, acc2[i][1]);
            acc2[i][0] = fma2(x1, wq1.x, acc2[i][0]);
            acc2[i][1] = fma2(x1, wq1.y, acc2[i][1]);
            acc2[i][0] = fma2(x2, wq2.x, acc2[i][0]);
            acc2[i][1] = fma2(x2, wq2.y, acc2[i][1]);
            acc2[i][0] = fma2(x3, wq3.x, acc2[i][0]);
            acc2[i][1] = fma2(x3, wq3.y, acc2[i][1]);
        }
    }

    const float4 bb = *(const float4*)&b[c0];
    #pragma unroll
    for (int i = 0; i < 8; i++) {
        float a0, a1, a2, a3;
        unpack2(acc2[i][0], a0, a1);
        unpack2(acc2[i][1], a2, a3);
        a0 += bb.x; a1 += bb.y; a2 += bb.z; a3 += bb.w;
        float s = a0 * a0 + a1 * a1 + a2 * a2 + a3 * a3;
        #pragma unroll
        for (int off = 16; off; off >>= 1) s += __shfl_xor_sync(0xffffffffu, s, off);
        const int node = nb + n0 + i;
        if (node < N) {
            const float sc = 1.8f / fmaxf(sqrtf(s), 1e-12f);
            __half2 h0 = __float22half2_rn(make_float2(a0 * sc, a1 * sc));
            __half2 h1 = __float22half2_rn(make_float2(a2 * sc, a3 * sc));
            uint2 o;
            o.x = *(uint32_t*)&h0;
            o.y = *(uint32_t*)&h1;
            *(uint2*)&Hout[(size_t)node * D + c0] = o;
        }
    }
}

// -------- GEMM layer 1 (graph-independent): X from global --------
__global__ void __launch_bounds__(GTHREADS, 2)
gemm_norm_k(const float* __restrict__ X,
            const float* __restrict__ W,
            const float* __restrict__ b,
            __half* __restrict__ Hout,
            int N)
{
    extern __shared__ float sm[];
    float* ws = sm;
    float* xs = sm + D * WS_STRIDE;
    const int tid = threadIdx.x;
    const int nb  = blockIdx.x * TM;

    for (int i = tid; i < D * D; i += GTHREADS) {
        int c = i >> 7, k = i & (D - 1);
        ws[k * WS_STRIDE + c] = W[i];
    }
    for (int i = tid; i < TM * D; i += GTHREADS) {
        int node = nb + (i >> 7);
        xs[i] = (node < N) ? X[(size_t)node * D + (i & (D - 1))] : 0.f;
    }
    __syncthreads();
    gemm_core(ws, xs, b, Hout, nb, N, tid);
}

// -------- per-edge accumulate (fp16 row, scaled by nO[s]) --------
__device__ __forceinline__ void acc_row(float4& acc, const __half* __restrict__ h,
                                        int s, float sc, int j4) {
    uint2 u = *(const uint2*)&h[(size_t)s * D + j4];
    __half2 p0 = *(__half2*)&u.x;
    __half2 p1 = *(__half2*)&u.y;
    float2 f0 = __half22float2(p0);
    float2 f1 = __half22float2(p1);
    acc.x = fmaf(sc, f0.x, acc.x);
    acc.y = fmaf(sc, f0.y, acc.y);
    acc.z = fmaf(sc, f1.x, acc.z);
    acc.w = fmaf(sc, f1.y, acc.w);
}

// warp-cooperative gather of one node's aggregate (lane owns cols j4..j4+3)
__device__ __forceinline__ float4 gather_node(const __half* __restrict__ h,
                                              int node, int lane, int j4)
{
    const int start = g_rowptr[node];
    const int end   = g_rowptr[node + 1];
    float4 acc = make_float4(0.f, 0.f, 0.f, 0.f);
    for (int base = start; base < end; base += 32) {
        const int e = base + lane;
        const int s = (e < end) ? g_esrc[e] : 0;
        const int cnt = min(32, end - base);
        int j = 0;
        for (; j + 8 <= cnt; j += 8) {
            #pragma unroll
            for (int q = 0; q < 8; q++) {
                int sq = __shfl_sync(0xffffffffu, s, j + q);
                acc_row(acc, h, sq, g_nO[sq], j4);
            }
        }
        for (; j < cnt; j++) {
            int sq = __shfl_sync(0xffffffffu, s, j);
            acc_row(acc, h, sq, g_nO[sq], j4);
        }
    }
    const float sc = g_nI[node];
    acc.x *= sc; acc.y *= sc; acc.z *= sc; acc.w *= sc;
    return acc;
}

// -------- fused gather + GEMM layer 2 (reads g_h, writes g_h2 — distinct) --------
__global__ void __launch_bounds__(GTHREADS, 2)
fused_gather_gemm_k(const __half* __restrict__ hin,
                    const float* __restrict__ W,
                    const float* __restrict__ b,
                    __half* __restrict__ Hout,
                    int N)
{
    extern __shared__ float sm[];
    float* ws = sm;
    float* xs = sm + D * WS_STRIDE;
    const int tid  = threadIdx.x;
    const int nb   = blockIdx.x * TM;
    const int lane = tid & 31;
    const int w    = tid >> 5;
    const int j4   = lane * 4;

    // W load+transpose (issued first: overlaps with gather latency)
    for (int i = tid; i < D * D; i += GTHREADS) {
        int c = i >> 7, k = i & (D - 1);
        ws[k * WS_STRIDE + c] = W[i];
    }

    // gather this warp's 8 rows directly into xs
    #pragma unroll 1
    for (int i = 0; i < 8; i++) {
        const int r = w * 8 + i;
        const int node = nb + r;
        float4 acc = make_float4(0.f, 0.f, 0.f, 0.f);
        if (node < N) acc = gather_node(hin, node, lane, j4);
        *(float4*)&xs[r * D + j4] = acc;
    }
    __syncthreads();
    gemm_core(ws, xs, b, Hout, nb, N, tid);
}

// -------- final gather: out[d,:] = nI[d] * sum nO[s]*h2[s,:] (fp32 out) --------
__global__ void gather_k(const __half* __restrict__ h,
                         float* __restrict__ out,
                         int N)
{
    const int node = blockIdx.x * 8 + (threadIdx.x >> 5);
    if (node >= N) return;
    const int lane = threadIdx.x & 31;
    const int j4 = lane * 4;
    float4 acc = gather_node(h, node, lane, j4);
    *(float4*)&out[(size_t)node * D + j4] = acc;
}

extern "C" void kernel_launch(void* const* d_in, const int* in_sizes, int n_in,
                              void* d_out, int out_size)
{
    const float* x   = (const float*)d_in[0];
    const float* W1  = (const float*)d_in[1];
    const float* b1  = (const float*)d_in[2];
    const float* W2  = (const float*)d_in[3];
    const float* b2  = (const float*)d_in[4];
    const int*   src = (const int*)d_in[5];
    const int*   dst = (const int*)d_in[6];
    float* out = (float*)d_out;

    const int N = in_sizes[0] / D;
    const int E = in_sizes[5];

    __half *h_ptr, *h2_ptr;
    cudaGetSymbolAddress((void**)&h_ptr,  g_h);
    cudaGetSymbolAddress((void**)&h2_ptr, g_h2);

    const int SMEM_BYTES = (D * WS_STRIDE + TM * D) * (int)sizeof(float);
    cudaFuncSetAttribute(gemm_norm_k, cudaFuncAttributeMaxDynamicSharedMemorySize, SMEM_BYTES);
    cudaFuncSetAttribute(fused_gather_gemm_k, cudaFuncAttributeMaxDynamicSharedMemorySize, SMEM_BYTES);

    const int nBlkGemm   = (N + TM - 1) / TM;
    const int nBlkNode   = (N + 255) / 256;
    const int nBlkEdge   = (E + 255) / 256;
    const int nBlkScan   = (N + SCAN_T - 1) / SCAN_T;
    const int nBlkGather = (N + 7) / 8;

    // Launch order puts gemm1 at slot #4 (ncu profiles launch #4).
    zero_deg_k<<<nBlkNode, 256>>>(N);                              // 1
    degree_k<<<nBlkEdge, 256>>>(src, dst, E);                      // 2
    scan_block_k<<<nBlkScan, SCAN_T>>>(N);                         // 3
    gemm_norm_k<<<nBlkGemm, GTHREADS, SMEM_BYTES>>>(x, W1, b1, h_ptr, N);  // 4 <- profiled
    scan_bsum_k<<<1, 512>>>(nBlkScan);                             // 5
    scan_add_norm_k<<<nBlkScan, SCAN_T>>>(N);                      // 6
    fill_k<<<nBlkEdge, 256>>>(src, dst, E);                        // 7

    // layer 2 fused: gather(g_h) -> smem tile -> GEMM -> g_h2
    fused_gather_gemm_k<<<nBlkGemm, GTHREADS, SMEM_BYTES>>>(h_ptr, W2, b2, h2_ptr, N); // 8

    // final aggregation (reads g_h2) -> out
    gather_k<<<nBlkGather, 256>>>(h2_ptr, out, N);                 // 9
}

// round 8
// speedup vs baseline: 1.6304x; 1.6304x over previous
#include <cuda_runtime.h>
#include <cuda_fp16.h>
#include <cuda_bf16.h>
#include <cstdint>

#define D        128
#define MAXN     100000
#define MAXE     1600000
#define SCAN_T   256

// ---- mma GEMM tile config ----
#define M_TILE   256
#define GT       512            // threads (16 warps)
#define AS       136            // padded row stride (bf16 elems): 272B -> conflict-free ldmatrix
#define A_HI     0
#define A_LO     69632          // 256*136*2
#define W_HI     139264
#define W_LO     174080         // + 128*136*2
#define SM_BIAS  208896
#define SMEMTOT  209920

// -------- device scratch --------
__device__ __half g_h[MAXN * D];      // post-GEMM h (normalize*1.8), fp16
__device__ float  g_agg[MAXN * D];    // layer-1 aggregate (fp32, feeds GEMM2)
__device__ int    g_degO[MAXN];
__device__ int    g_degI[MAXN];
__device__ float  g_nO[MAXN];
__device__ float  g_nI[MAXN];
__device__ int    g_rowptr[MAXN + 1];
__device__ int    g_esrc[MAXE];
__device__ int    g_bsum[512];
__device__ int    g_fill[MAXN + 1];

// -------- degree --------
__global__ void zero_deg_k(int n) {
    int i = blockIdx.x * blockDim.x + threadIdx.x;
    if (i < n) { g_degO[i] = 0; g_degI[i] = 0; }
}
__global__ void degree_k(const int* __restrict__ src, const int* __restrict__ dst, int E) {
    int e = blockIdx.x * blockDim.x + threadIdx.x;
    if (e < E) { atomicAdd(&g_degO[src[e]], 1); atomicAdd(&g_degI[dst[e]], 1); }
}

// -------- prefix scan over degI -> rowptr; fused norms + cursor seed --------
__global__ void scan_block_k(int n) {
    __shared__ int s[SCAN_T];
    int i = blockIdx.x * SCAN_T + threadIdx.x;
    int v = (i < n) ? g_degI[i] : 0;
    s[threadIdx.x] = v;
    __syncthreads();
    #pragma unroll
    for (int off = 1; off < SCAN_T; off <<= 1) {
        int t = (threadIdx.x >= off) ? s[threadIdx.x - off] : 0;
        __syncthreads();
        s[threadIdx.x] += t;
        __syncthreads();
    }
    if (i < n) g_rowptr[i + 1] = s[threadIdx.x];
    if (threadIdx.x == SCAN_T - 1) g_bsum[blockIdx.x] = s[SCAN_T - 1];
}
__global__ void scan_bsum_k(int nb) {
    __shared__ int s[512];
    int v = (threadIdx.x < nb) ? g_bsum[threadIdx.x] : 0;
    s[threadIdx.x] = v;
    __syncthreads();
    #pragma unroll
    for (int off = 1; off < 512; off <<= 1) {
        int t = (threadIdx.x >= off) ? s[threadIdx.x - off] : 0;
        __syncthreads();
        s[threadIdx.x] += t;
        __syncthreads();
    }
    if (threadIdx.x < nb) g_bsum[threadIdx.x] = s[threadIdx.x] - v;
}
__global__ void scan_add_norm_k(int n) {
    int i = blockIdx.x * SCAN_T + threadIdx.x;
    if (i < n) {
        int v = g_rowptr[i + 1] + g_bsum[blockIdx.x];
        g_rowptr[i + 1] = v;
        g_fill[i + 1]   = v;
        g_nO[i] = rsqrtf(fmaxf((float)g_degO[i], 1.0f));
        g_nI[i] = rsqrtf(fmaxf((float)g_degI[i], 1.0f));
    }
    if (i == 0) { g_rowptr[0] = 0; g_fill[0] = 0; }
}
__global__ void fill_k(const int* __restrict__ src, const int* __restrict__ dst, int E) {
    int e = blockIdx.x * blockDim.x + threadIdx.x;
    if (e < E) {
        int pos = atomicAdd(&g_fill[dst[e]], 1);
        g_esrc[pos] = src[e];
    }
}

// -------- mma helpers --------
__device__ __forceinline__ uint32_t smem_u32(const void* p) {
    uint32_t a;
    asm("{ .reg .u64 t; cvta.to.shared.u64 t, %1; cvt.u32.u64 %0, t; }" : "=r"(a) : "l"(p));
    return a;
}
__device__ __forceinline__ void ldsm4(uint32_t& r0, uint32_t& r1, uint32_t& r2, uint32_t& r3,
                                      uint32_t addr) {
    asm volatile("ldmatrix.sync.aligned.m8n8.x4.shared.b16 {%0,%1,%2,%3}, [%4];"
                 : "=r"(r0), "=r"(r1), "=r"(r2), "=r"(r3) : "r"(addr));
}
__device__ __forceinline__ void mma16816(float* c, const uint32_t* a, uint32_t b0, uint32_t b1) {
    asm volatile(
        "mma.sync.aligned.m16n8k16.row.col.f32.bf16.bf16.f32 "
        "{%0,%1,%2,%3}, {%4,%5,%6,%7}, {%8,%9}, {%0,%1,%2,%3};"
        : "+f"(c[0]), "+f"(c[1]), "+f"(c[2]), "+f"(c[3])
        : "r"(a[0]), "r"(a[1]), "r"(a[2]), "r"(a[3]), "r"(b0), "r"(b1));
}
// split float -> (hi, lo) bf16 pair packed as two bf162 words for 4 consecutive values
__device__ __forceinline__ void split4(float4 v, uint32_t& h01, uint32_t& h23,
                                       uint32_t& l01, uint32_t& l23) {
    __nv_bfloat162 a = __floats2bfloat162_rn(v.x, v.y);
    __nv_bfloat162 b = __floats2bfloat162_rn(v.z, v.w);
    float r0 = v.x - __bfloat162float(__low2bfloat16(a));
    float r1 = v.y - __bfloat162float(__high2bfloat16(a));
    float r2 = v.z - __bfloat162float(__low2bfloat16(b));
    float r3 = v.w - __bfloat162float(__high2bfloat16(b));
    __nv_bfloat162 c = __floats2bfloat162_rn(r0, r1);
    __nv_bfloat162 d = __floats2bfloat162_rn(r2, r3);
    h01 = *(uint32_t*)&a; h23 = *(uint32_t*)&b;
    l01 = *(uint32_t*)&c; l23 = *(uint32_t*)&d;
}

// -------- tensor-core GEMM + bias + L2-normalize*1.8 -> fp16 --------
// Hout[n,:] = normalize(X[n,:] @ W^T + b) * 1.8
// 3-term bf16 split: Ah*Wh + Ah*Wl + Al*Wh  (~fp32 accuracy)
__global__ void __launch_bounds__(GT, 1)
gemm_norm_k(const float* __restrict__ X,
            const float* __restrict__ W,
            const float* __restrict__ b,
            __half* __restrict__ Hout,
            int N)
{
    extern __shared__ char smem[];
    const uint32_t sb = smem_u32(smem);
    const int tid  = threadIdx.x;
    const int wid  = tid >> 5;
    const int lane = tid & 31;
    const int nb   = blockIdx.x * M_TILE;

    // ---- load X tile, split to bf16 hi/lo (padded rows) ----
    #pragma unroll
    for (int t = tid; t < M_TILE * 32; t += GT) {       // float4 units
        int m = t >> 5, k = (t & 31) * 4;
        int node = nb + m;
        float4 v = make_float4(0.f, 0.f, 0.f, 0.f);
        if (node < N) v = *(const float4*)&X[(size_t)node * D + k];
        uint32_t h01, h23, l01, l23;
        split4(v, h01, h23, l01, l23);
        uint32_t off = (uint32_t)(m * AS + k) * 2;
        *(uint2*)(smem + A_HI + off) = make_uint2(h01, h23);
        *(uint2*)(smem + A_LO + off) = make_uint2(l01, l23);
    }
    // ---- load W (row-major [c][k]), split ----
    #pragma unroll
    for (int t = tid; t < D * 32; t += GT) {
        int c = t >> 5, k = (t & 31) * 4;
        float4 v = *(const float4*)&W[(size_t)c * D + k];
        uint32_t h01, h23, l01, l23;
        split4(v, h01, h23, l01, l23);
        uint32_t off = (uint32_t)(c * AS + k) * 2;
        *(uint2*)(smem + W_HI + off) = make_uint2(h01, h23);
        *(uint2*)(smem + W_LO + off) = make_uint2(l01, l23);
    }
    if (tid < D) ((float*)(smem + SM_BIAS))[tid] = b[tid];
    __syncthreads();

    // ---- per-warp m16 x n128 strip ----
    const int g   = lane & 7;
    const int sel = lane >> 3;
    // A ldmatrix lane addressing: mats 0:(m0-7,k0) 1:(m8-15,k0) 2:(m0-7,k+8) 3:(m8-15,k+8)
    const int aRow  = wid * 16 + ((sel & 1) << 3) + g;
    const int aKoff = (sel & 2) << 2;  // 0 or 8
    const uint32_t aHiBase = sb + A_HI + (uint32_t)(aRow * AS + aKoff) * 2;
    const uint32_t aLoBase = aHiBase + (A_LO - A_HI);
    // B ldmatrix lane addressing (per j): mats 0:(n0-7,k0) 1:(n0-7,k+8) 2:(n8-15,k0) 3:(n8-15,k+8)
    const int bnOff = ((sel & 2) << 2) + g;  // +8 rows if sel bit1
    const int bkOff = (sel & 1) << 3;
    const uint32_t wHiBase = sb + W_HI + (uint32_t)bkOff * 2;
    const uint32_t wLoBase = sb + W_LO + (uint32_t)bkOff * 2;

    float c[16][4];
    #pragma unroll
    for (int i = 0; i < 16; i++) { c[i][0]=0.f; c[i][1]=0.f; c[i][2]=0.f; c[i][3]=0.f; }

    #pragma unroll 2
    for (int ks = 0; ks < 8; ks++) {
        const uint32_t k0b = (uint32_t)(ks * 16) * 2;
        uint32_t ah[4], al[4];
        ldsm4(ah[0], ah[1], ah[2], ah[3], aHiBase + k0b);
        ldsm4(al[0], al[1], al[2], al[3], aLoBase + k0b);
        #pragma unroll
        for (int j = 0; j < 8; j++) {
            const uint32_t rowoff = (uint32_t)((16 * j + bnOff) * AS) * 2 + k0b;
            uint32_t bh[4], bl[4];
            ldsm4(bh[0], bh[1], bh[2], bh[3], wHiBase + rowoff);
            ldsm4(bl[0], bl[1], bl[2], bl[3], wLoBase + rowoff);
            // ntile 2j
            mma16816(c[2*j],   ah, bh[0], bh[1]);
            mma16816(c[2*j],   ah, bl[0], bl[1]);
            mma16816(c[2*j],   al, bh[0], bh[1]);
            // ntile 2j+1
            mma16816(c[2*j+1], ah, bh[2], bh[3]);
            mma16816(c[2*j+1], ah, bl[2], bl[3]);
            mma16816(c[2*j+1], al, bh[2], bh[3]);
        }
    }

    // ---- epilogue: bias, row L2-norm (quad reduce), scale, fp16 store ----
    const float* bs = (const float*)(smem + SM_BIAS);
    const int q    = lane >> 2;           // row-within-strip 0..7
    const int cpos = (lane & 3) * 2;      // col pair offset within ntile
    float s0 = 0.f, s1 = 0.f;
    #pragma unroll
    for (int nt = 0; nt < 16; nt++) {
        const int col = nt * 8 + cpos;
        const float b0 = bs[col], b1 = bs[col + 1];
        c[nt][0] += b0; c[nt][1] += b1;
        c[nt][2] += b0; c[nt][3] += b1;
        s0 += c[nt][0]*c[nt][0] + c[nt][1]*c[nt][1];
        s1 += c[nt][2]*c[nt][2] + c[nt][3]*c[nt][3];
    }
    s0 += __shfl_xor_sync(0xffffffffu, s0, 1);
    s0 += __shfl_xor_sync(0xffffffffu, s0, 2);
    s1 += __shfl_xor_sync(0xffffffffu, s1, 1);
    s1 += __shfl_xor_sync(0xffffffffu, s1, 2);

    const int r0 = nb + wid * 16 + q;
    const int r1 = r0 + 8;
    const float sc0 = 1.8f / fmaxf(sqrtf(s0), 1e-12f);
    const float sc1 = 1.8f / fmaxf(sqrtf(s1), 1e-12f);
    #pragma unroll
    for (int nt = 0; nt < 16; nt++) {
        const int col = nt * 8 + cpos;
        if (r0 < N) {
            __half2 h = __float22half2_rn(make_float2(c[nt][0] * sc0, c[nt][1] * sc0));
            *(__half2*)&Hout[(size_t)r0 * D + col] = h;
        }
        if (r1 < N) {
            __half2 h = __float22half2_rn(make_float2(c[nt][2] * sc1, c[nt][3] * sc1));
            *(__half2*)&Hout[(size_t)r1 * D + col] = h;
        }
    }
}

// -------- CSR gather: out[d,:] = nI[d] * sum nO[s]*h[s,:] (fp32 out) --------
__device__ __forceinline__ void acc_row(float4& acc, const __half* __restrict__ h,
                                        int s, float sc, int j4) {
    uint2 u = *(const uint2*)&h[(size_t)s * D + j4];
    __half2 p0 = *(__half2*)&u.x;
    __half2 p1 = *(__half2*)&u.y;
    float2 f0 = __half22float2(p0);
    float2 f1 = __half22float2(p1);
    acc.x = fmaf(sc, f0.x, acc.x);
    acc.y = fmaf(sc, f0.y, acc.y);
    acc.z = fmaf(sc, f1.x, acc.z);
    acc.w = fmaf(sc, f1.y, acc.w);
}

__global__ void gather_k(const __half* __restrict__ h,
                         float* __restrict__ out,
                         int N)
{
    const int node = blockIdx.x * 8 + (threadIdx.x >> 5);
    if (node >= N) return;
    const int lane = threadIdx.x & 31;
    const int j4 = lane * 4;
    const int start = g_rowptr[node];
    const int end   = g_rowptr[node + 1];

    float4 acc = make_float4(0.f, 0.f, 0.f, 0.f);
    for (int base = start; base < end; base += 32) {
        const int e = base + lane;
        const int s = (e < end) ? g_esrc[e] : 0;
        const int cnt = min(32, end - base);
        int j = 0;
        for (; j + 8 <= cnt; j += 8) {
            #pragma unroll
            for (int qq = 0; qq < 8; qq++) {
                int sq = __shfl_sync(0xffffffffu, s, j + qq);
                acc_row(acc, h, sq, g_nO[sq], j4);
            }
        }
        for (; j < cnt; j++) {
            int sq = __shfl_sync(0xffffffffu, s, j);
            acc_row(acc, h, sq, g_nO[sq], j4);
        }
    }
    const float sc = g_nI[node];
    acc.x *= sc; acc.y *= sc; acc.z *= sc; acc.w *= sc;
    *(float4*)&out[(size_t)node * D + j4] = acc;
}

extern "C" void kernel_launch(void* const* d_in, const int* in_sizes, int n_in,
                              void* d_out, int out_size)
{
    const float* x   = (const float*)d_in[0];
    const float* W1  = (const float*)d_in[1];
    const float* b1  = (const float*)d_in[2];
    const float* W2  = (const float*)d_in[3];
    const float* b2  = (const float*)d_in[4];
    const int*   src = (const int*)d_in[5];
    const int*   dst = (const int*)d_in[6];
    float* out = (float*)d_out;

    const int N = in_sizes[0] / D;
    const int E = in_sizes[5];

    __half* h_ptr;
    float*  agg_ptr;
    cudaGetSymbolAddress((void**)&h_ptr,   g_h);
    cudaGetSymbolAddress((void**)&agg_ptr, g_agg);

    cudaFuncSetAttribute(gemm_norm_k, cudaFuncAttributeMaxDynamicSharedMemorySize, SMEMTOT);

    const int nBlkGemm   = (N + M_TILE - 1) / M_TILE;
    const int nBlkNode   = (N + 255) / 256;
    const int nBlkEdge   = (E + 255) / 256;
    const int nBlkScan   = (N + SCAN_T - 1) / SCAN_T;
    const int nBlkGather = (N + 7) / 8;

    // gemm1 kept at launch slot #4 (ncu profiles launch #4); it is graph-independent.
    zero_deg_k<<<nBlkNode, 256>>>(N);                               // 1
    degree_k<<<nBlkEdge, 256>>>(src, dst, E);                       // 2
    scan_block_k<<<nBlkScan, SCAN_T>>>(N);                          // 3
    gemm_norm_k<<<nBlkGemm, GT, SMEMTOT>>>(x, W1, b1, h_ptr, N);    // 4 <- profiled
    scan_bsum_k<<<1, 512>>>(nBlkScan);                              // 5
    scan_add_norm_k<<<nBlkScan, SCAN_T>>>(N);                       // 6
    fill_k<<<nBlkEdge, 256>>>(src, dst, E);                         // 7

    gather_k<<<nBlkGather, 256>>>(h_ptr, agg_ptr, N);               // 8
    gemm_norm_k<<<nBlkGemm, GT, SMEMTOT>>>(agg_ptr, W2, b2, h_ptr, N); // 9
    gather_k<<<nBlkGather, 256>>>(h_ptr, out, N);                   // 10
}

// round 9
// speedup vs baseline: 1.7117x; 1.0498x over previous
#include <cuda_runtime.h>
#include <cuda_fp16.h>
#include <cuda_bf16.h>
#include <cstdint>

#define D        128
#define MAXN     100000
#define MAXE     1600000

// ---- mma GEMM tile config ----
#define M_TILE   256
#define GT       512            // threads (16 warps)
#define AS       136            // padded row stride (bf16 elems): 272B -> conflict-free ldmatrix
#define A_HI     0
#define A_LO     69632          // 256*136*2
#define W_HI     139264
#define W_LO     174080         // + 128*136*2
#define SM_BIAS  208896
#define SMEMTOT  209920

// -------- device scratch --------
__device__ __half g_h[MAXN * D];      // post-GEMM h (normalize*1.8), fp16
__device__ float  g_agg[MAXN * D];    // layer-1 aggregate (fp32, feeds GEMM2)
__device__ int    g_degO[MAXN];
__device__ int    g_degI[MAXN];
__device__ float  g_nO[MAXN];
__device__ float  g_nI[MAXN];
__device__ int    g_rowptr[MAXN + 1];
__device__ int    g_esrc[MAXE];
__device__ int    g_fill[MAXN + 1];
// decoupled-lookback scan state
__device__ unsigned long long g_state[512];   // (value<<2)|status: 0 invalid,1 aggregate,2 inclusive
__device__ int    g_ticket;

// -------- degree + scan-state reset --------
__global__ void zero_deg_k(int n) {
    int i = blockIdx.x * blockDim.x + threadIdx.x;
    if (i < n) { g_degO[i] = 0; g_degI[i] = 0; }
    if (i < 512) g_state[i] = 0ull;
    if (i == 0)  g_ticket = 0;
}
__global__ void degree_k(const int* __restrict__ src, const int* __restrict__ dst, int E) {
    int e = blockIdx.x * blockDim.x + threadIdx.x;
    if (e < E) { atomicAdd(&g_degO[src[e]], 1); atomicAdd(&g_degI[dst[e]], 1); }
}

// -------- single-kernel decoupled-lookback scan over degI -> rowptr --------
// Also writes norms (nO,nI) and seeds the CSR fill cursor.
__global__ void __launch_bounds__(256, 8)
scan_fused_k(int n) {
    __shared__ int s_rank;
    __shared__ int s_wsum[8];
    __shared__ int s_prefix;
    const int tid  = threadIdx.x;
    const int lane = tid & 31;
    const int wid  = tid >> 5;

    if (tid == 0) s_rank = atomicAdd(&g_ticket, 1);
    __syncthreads();
    const int rank = s_rank;
    const int i = rank * 256 + tid;

    int v = (i < n) ? g_degI[i] : 0;
    // inclusive warp scan
    int x = v;
    #pragma unroll
    for (int o = 1; o < 32; o <<= 1) {
        int t = __shfl_up_sync(0xffffffffu, x, o);
        if (lane >= o) x += t;
    }
    if (lane == 31) s_wsum[wid] = x;
    __syncthreads();
    if (wid == 0) {
        int ws = (lane < 8) ? s_wsum[lane] : 0;
        #pragma unroll
        for (int o = 1; o < 8; o <<= 1) {
            int t = __shfl_up_sync(0xffffffffu, ws, o);
            if (lane >= o) ws += t;
        }
        if (lane < 8) s_wsum[lane] = ws;
    }
    __syncthreads();
    const int incl  = x + (wid ? s_wsum[wid - 1] : 0);
    const int total = s_wsum[7];

    if (tid == 0)
        atomicExch(&g_state[rank], ((unsigned long long)(unsigned)total << 2) | 1ull);

    // warp 0: warp-parallel lookback
    if (wid == 0) {
        unsigned long long prefix = 0;
        int p = rank - 1;
        while (p >= 0) {
            const int idx = p - lane;
            unsigned long long sv = (idx >= 0) ? atomicAdd(&g_state[idx], 0ull) : 2ull;
            const unsigned st = (unsigned)(sv & 3ull);
            if (__ballot_sync(0xffffffffu, st == 0u)) continue;   // some invalid: retry window
            const unsigned inclm = __ballot_sync(0xffffffffu, st == 2u);
            unsigned long long add;
            if (inclm) {
                const int fi = __ffs(inclm) - 1;   // closest inclusive predecessor
                add = (lane <= fi) ? (sv >> 2) : 0ull;
            } else {
                add = sv >> 2;                      // all aggregates: take whole window
            }
            #pragma unroll
            for (int o = 16; o; o >>= 1) add += __shfl_xor_sync(0xffffffffu, add, o);
            prefix += add;
            if (inclm) break;
            p -= 32;
        }
        if (lane == 0) {
            atomicExch(&g_state[rank],
                       ((prefix + (unsigned long long)(unsigned)total) << 2) | 2ull);
            s_prefix = (int)prefix;
        }
    }
    __syncthreads();
    const int pre = s_prefix;

    if (i < n) {
        const int val = pre + incl;
        g_rowptr[i + 1] = val;
        g_fill[i + 1]   = val;
        g_nO[i] = rsqrtf(fmaxf((float)g_degO[i], 1.0f));
        g_nI[i] = rsqrtf(fmaxf((float)g_degI[i], 1.0f));
    }
    if (i == 0) { g_rowptr[0] = 0; g_fill[0] = 0; }
}

__global__ void fill_k(const int* __restrict__ src, const int* __restrict__ dst, int E) {
    int e = blockIdx.x * blockDim.x + threadIdx.x;
    if (e < E) {
        int pos = atomicAdd(&g_fill[dst[e]], 1);
        g_esrc[pos] = src[e];
    }
}

// -------- mma helpers --------
__device__ __forceinline__ uint32_t smem_u32(const void* p) {
    uint32_t a;
    asm("{ .reg .u64 t; cvta.to.shared.u64 t, %1; cvt.u32.u64 %0, t; }" : "=r"(a) : "l"(p));
    return a;
}
__device__ __forceinline__ void ldsm4(uint32_t& r0, uint32_t& r1, uint32_t& r2, uint32_t& r3,
                                      uint32_t addr) {
    asm volatile("ldmatrix.sync.aligned.m8n8.x4.shared.b16 {%0,%1,%2,%3}, [%4];"
                 : "=r"(r0), "=r"(r1), "=r"(r2), "=r"(r3) : "r"(addr));
}
__device__ __forceinline__ void mma16816(float* c, const uint32_t* a, uint32_t b0, uint32_t b1) {
    asm volatile(
        "mma.sync.aligned.m16n8k16.row.col.f32.bf16.bf16.f32 "
        "{%0,%1,%2,%3}, {%4,%5,%6,%7}, {%8,%9}, {%0,%1,%2,%3};"
        : "+f"(c[0]), "+f"(c[1]), "+f"(c[2]), "+f"(c[3])
        : "r"(a[0]), "r"(a[1]), "r"(a[2]), "r"(a[3]), "r"(b0), "r"(b1));
}
__device__ __forceinline__ void split4(float4 v, uint32_t& h01, uint32_t& h23,
                                       uint32_t& l01, uint32_t& l23) {
    __nv_bfloat162 a = __floats2bfloat162_rn(v.x, v.y);
    __nv_bfloat162 b = __floats2bfloat162_rn(v.z, v.w);
    float r0 = v.x - __bfloat162float(__low2bfloat16(a));
    float r1 = v.y - __bfloat162float(__high2bfloat16(a));
    float r2 = v.z - __bfloat162float(__low2bfloat16(b));
    float r3 = v.w - __bfloat162float(__high2bfloat16(b));
    __nv_bfloat162 c = __floats2bfloat162_rn(r0, r1);
    __nv_bfloat162 d = __floats2bfloat162_rn(r2, r3);
    h01 = *(uint32_t*)&a; h23 = *(uint32_t*)&b;
    l01 = *(uint32_t*)&c; l23 = *(uint32_t*)&d;
}

// -------- tensor-core GEMM + bias + L2-normalize*1.8 -> fp16 (identical to R8) --------
__global__ void __launch_bounds__(GT, 1)
gemm_norm_k(const float* __restrict__ X,
            const float* __restrict__ W,
            const float* __restrict__ b,
            __half* __restrict__ Hout,
            int N)
{
    extern __shared__ char smem[];
    const uint32_t sb = smem_u32(smem);
    const int tid  = threadIdx.x;
    const int wid  = tid >> 5;
    const int lane = tid & 31;
    const int nb   = blockIdx.x * M_TILE;

    #pragma unroll
    for (int t = tid; t < M_TILE * 32; t += GT) {
        int m = t >> 5, k = (t & 31) * 4;
        int node = nb + m;
        float4 v = make_float4(0.f, 0.f, 0.f, 0.f);
        if (node < N) v = *(const float4*)&X[(size_t)node * D + k];
        uint32_t h01, h23, l01, l23;
        split4(v, h01, h23, l01, l23);
        uint32_t off = (uint32_t)(m * AS + k) * 2;
        *(uint2*)(smem + A_HI + off) = make_uint2(h01, h23);
        *(uint2*)(smem + A_LO + off) = make_uint2(l01, l23);
    }
    #pragma unroll
    for (int t = tid; t < D * 32; t += GT) {
        int c = t >> 5, k = (t & 31) * 4;
        float4 v = *(const float4*)&W[(size_t)c * D + k];
        uint32_t h01, h23, l01, l23;
        split4(v, h01, h23, l01, l23);
        uint32_t off = (uint32_t)(c * AS + k) * 2;
        *(uint2*)(smem + W_HI + off) = make_uint2(h01, h23);
        *(uint2*)(smem + W_LO + off) = make_uint2(l01, l23);
    }
    if (tid < D) ((float*)(smem + SM_BIAS))[tid] = b[tid];
    __syncthreads();

    const int g   = lane & 7;
    const int sel = lane >> 3;
    const int aRow  = wid * 16 + ((sel & 1) << 3) + g;
    const int aKoff = (sel & 2) << 2;
    const uint32_t aHiBase = sb + A_HI + (uint32_t)(aRow * AS + aKoff) * 2;
    const uint32_t aLoBase = aHiBase + (A_LO - A_HI);
    const int bnOff = ((sel & 2) << 2) + g;
    const int bkOff = (sel & 1) << 3;
    const uint32_t wHiBase = sb + W_HI + (uint32_t)bkOff * 2;
    const uint32_t wLoBase = sb + W_LO + (uint32_t)bkOff * 2;

    float c[16][4];
    #pragma unroll
    for (int i = 0; i < 16; i++) { c[i][0]=0.f; c[i][1]=0.f; c[i][2]=0.f; c[i][3]=0.f; }

    #pragma unroll 2
    for (int ks = 0; ks < 8; ks++) {
        const uint32_t k0b = (uint32_t)(ks * 16) * 2;
        uint32_t ah[4], al[4];
        ldsm4(ah[0], ah[1], ah[2], ah[3], aHiBase + k0b);
        ldsm4(al[0], al[1], al[2], al[3], aLoBase + k0b);
        #pragma unroll
        for (int j = 0; j < 8; j++) {
            const uint32_t rowoff = (uint32_t)((16 * j + bnOff) * AS) * 2 + k0b;
            uint32_t bh[4], bl[4];
            ldsm4(bh[0], bh[1], bh[2], bh[3], wHiBase + rowoff);
            ldsm4(bl[0], bl[1], bl[2], bl[3], wLoBase + rowoff);
            mma16816(c[2*j],   ah, bh[0], bh[1]);
            mma16816(c[2*j],   ah, bl[0], bl[1]);
            mma16816(c[2*j],   al, bh[0], bh[1]);
            mma16816(c[2*j+1], ah, bh[2], bh[3]);
            mma16816(c[2*j+1], ah, bl[2], bl[3]);
            mma16816(c[2*j+1], al, bh[2], bh[3]);
        }
    }

    const float* bs = (const float*)(smem + SM_BIAS);
    const int q    = lane >> 2;
    const int cpos = (lane & 3) * 2;
    float s0 = 0.f, s1 = 0.f;
    #pragma unroll
    for (int nt = 0; nt < 16; nt++) {
        const int col = nt * 8 + cpos;
        const float b0 = bs[col], b1 = bs[col + 1];
        c[nt][0] += b0; c[nt][1] += b1;
        c[nt][2] += b0; c[nt][3] += b1;
        s0 += c[nt][0]*c[nt][0] + c[nt][1]*c[nt][1];
        s1 += c[nt][2]*c[nt][2] + c[nt][3]*c[nt][3];
    }
    s0 += __shfl_xor_sync(0xffffffffu, s0, 1);
    s0 += __shfl_xor_sync(0xffffffffu, s0, 2);
    s1 += __shfl_xor_sync(0xffffffffu, s1, 1);
    s1 += __shfl_xor_sync(0xffffffffu, s1, 2);

    const int r0 = nb + wid * 16 + q;
    const int r1 = r0 + 8;
    const float sc0 = 1.8f / fmaxf(sqrtf(s0), 1e-12f);
    const float sc1 = 1.8f / fmaxf(sqrtf(s1), 1e-12f);
    #pragma unroll
    for (int nt = 0; nt < 16; nt++) {
        const int col = nt * 8 + cpos;
        if (r0 < N) {
            __half2 h = __float22half2_rn(make_float2(c[nt][0] * sc0, c[nt][1] * sc0));
            *(__half2*)&Hout[(size_t)r0 * D + col] = h;
        }
        if (r1 < N) {
            __half2 h = __float22half2_rn(make_float2(c[nt][2] * sc1, c[nt][3] * sc1));
            *(__half2*)&Hout[(size_t)r1 * D + col] = h;
        }
    }
}

// -------- CSR gather (identical to R8) --------
__device__ __forceinline__ void acc_row(float4& acc, const __half* __restrict__ h,
                                        int s, float sc, int j4) {
    uint2 u = *(const uint2*)&h[(size_t)s * D + j4];
    __half2 p0 = *(__half2*)&u.x;
    __half2 p1 = *(__half2*)&u.y;
    float2 f0 = __half22float2(p0);
    float2 f1 = __half22float2(p1);
    acc.x = fmaf(sc, f0.x, acc.x);
    acc.y = fmaf(sc, f0.y, acc.y);
    acc.z = fmaf(sc, f1.x, acc.z);
    acc.w = fmaf(sc, f1.y, acc.w);
}

__global__ void gather_k(const __half* __restrict__ h,
                         float* __restrict__ out,
                         int N)
{
    const int node = blockIdx.x * 8 + (threadIdx.x >> 5);
    if (node >= N) return;
    const int lane = threadIdx.x & 31;
    const int j4 = lane * 4;
    const int start = g_rowptr[node];
    const int end   = g_rowptr[node + 1];

    float4 acc = make_float4(0.f, 0.f, 0.f, 0.f);
    for (int base = start; base < end; base += 32) {
        const int e = base + lane;
        const int s = (e < end) ? g_esrc[e] : 0;
        const int cnt = min(32, end - base);
        int j = 0;
        for (; j + 8 <= cnt; j += 8) {
            #pragma unroll
            for (int qq = 0; qq < 8; qq++) {
                int sq = __shfl_sync(0xffffffffu, s, j + qq);
                acc_row(acc, h, sq, g_nO[sq], j4);
            }
        }
        for (; j < cnt; j++) {
            int sq = __shfl_sync(0xffffffffu, s, j);
            acc_row(acc, h, sq, g_nO[sq], j4);
        }
    }
    const float sc = g_nI[node];
    acc.x *= sc; acc.y *= sc; acc.z *= sc; acc.w *= sc;
    *(float4*)&out[(size_t)node * D + j4] = acc;
}

extern "C" void kernel_launch(void* const* d_in, const int* in_sizes, int n_in,
                              void* d_out, int out_size)
{
    const float* x   = (const float*)d_in[0];
    const float* W1  = (const float*)d_in[1];
    const float* b1  = (const float*)d_in[2];
    const float* W2  = (const float*)d_in[3];
    const float* b2  = (const float*)d_in[4];
    const int*   src = (const int*)d_in[5];
    const int*   dst = (const int*)d_in[6];
    float* out = (float*)d_out;

    const int N = in_sizes[0] / D;
    const int E = in_sizes[5];

    __half* h_ptr;
    float*  agg_ptr;
    cudaGetSymbolAddress((void**)&h_ptr,   g_h);
    cudaGetSymbolAddress((void**)&agg_ptr, g_agg);

    cudaFuncSetAttribute(gemm_norm_k, cudaFuncAttributeMaxDynamicSharedMemorySize, SMEMTOT);

    const int nBlkGemm   = (N + M_TILE - 1) / M_TILE;
    const int nBlkNode   = (N + 255) / 256;
    const int nBlkEdge   = (E + 255) / 256;
    const int nBlkScan   = (N + 255) / 256;
    const int nBlkGather = (N + 7) / 8;

    static cudaStream_t s_side = nullptr;
    static cudaEvent_t  ev_fork = nullptr, ev_join = nullptr;
    static int stream_ok = -1;
    if (stream_ok < 0) {
        stream_ok = (cudaStreamCreateWithFlags(&s_side, cudaStreamNonBlocking) == cudaSuccess &&
                     cudaEventCreateWithFlags(&ev_fork, cudaEventDisableTiming) == cudaSuccess &&
                     cudaEventCreateWithFlags(&ev_join, cudaEventDisableTiming) == cudaSuccess)
                    ? 1 : 0;
    }

    if (stream_ok) {
        cudaEventRecord(ev_fork, 0);
        cudaStreamWaitEvent(s_side, ev_fork, 0);

        zero_deg_k<<<nBlkNode, 256, 0, s_side>>>(N);                 // launch 1
        degree_k<<<nBlkEdge, 256, 0, s_side>>>(src, dst, E);         // 2
        scan_fused_k<<<nBlkScan, 256, 0, s_side>>>(N);               // 3
        gemm_norm_k<<<nBlkGemm, GT, SMEMTOT>>>(x, W1, b1, h_ptr, N); // 4 <- profiled (main)
        fill_k<<<nBlkEdge, 256, 0, s_side>>>(src, dst, E);           // 5
        cudaEventRecord(ev_join, s_side);
        cudaStreamWaitEvent(0, ev_join, 0);
    } else {
        zero_deg_k<<<nBlkNode, 256>>>(N);
        degree_k<<<nBlkEdge, 256>>>(src, dst, E);
        scan_fused_k<<<nBlkScan, 256>>>(N);
        gemm_norm_k<<<nBlkGemm, GT, SMEMTOT>>>(x, W1, b1, h_ptr, N);
        fill_k<<<nBlkEdge, 256>>>(src, dst, E);
    }

    gather_k<<<nBlkGather, 256>>>(h_ptr, agg_ptr, N);                // 6
    gemm_norm_k<<<nBlkGemm, GT, SMEMTOT>>>(agg_ptr, W2, b2, h_ptr, N); // 7
    gather_k<<<nBlkGather, 256>>>(h_ptr, out, N);                    // 8
}